// round 6
// baseline (speedup 1.0000x reference)
#include <cuda_runtime.h>
#include <cuda_bf16.h>
#include <cstdint>

// Problem constants (fixed by the reference setup_inputs)
#define N_USERS_C 200000
#define NN_C      300000          // N_USERS + N_ITEMS
#define D_C       64
#define NEDGES_C  1200000
#define NB1       293             // ceil(NN_C / 1024)
#define EB        4688            // ceil(NEDGES_C / 256)

// Scratch (device globals; zero-init at load).
// g_counts lifecycle per replay: hist fills -> scan1 reads+zeroes ->
// bucket uses as cursors (fills again) -> fused zeroes.
__device__ int  g_counts  [NN_C];
__device__ int  g_loc     [NN_C];      // block-local exclusive prefix
__device__ int  g_partials[NB1];       // per-1024-block totals -> exclusive
__device__ int2 g_edges   [NEDGES_C];  // (col, bitcast(val)) row-sorted
__device__ int  g_general;             // 1 if filt != eye(64)

// ---------------------------------------------------------------------------
// K0: per-row histogram + emb copy into out[:, 0:64] + filt check (block 0).
//     The copy's bandwidth overlaps the atomic-ALU-bound histogram.
// ---------------------------------------------------------------------------
__global__ void __launch_bounds__(256)
k_hist_copy(const int* __restrict__ adj_rows,
            const float* __restrict__ filt,
            const float* __restrict__ user_emb,
            const float* __restrict__ item_emb,
            float* __restrict__ out) {
    if (blockIdx.x == 0) {
        __shared__ int s_bad;
        if (threadIdx.x == 0) s_bad = 0;
        __syncthreads();
        int bad = 0;
        for (int i = threadIdx.x; i < D_C * D_C; i += 256) {
            float expect = ((i >> 6) == (i & 63)) ? 1.0f : 0.0f;
            if (filt[i] != expect) bad = 1;
        }
        if (bad) atomicOr(&s_bad, 1);
        __syncthreads();
        if (threadIdx.x == 0) g_general = s_bad;
    }

    const int t = blockIdx.x * 256 + threadIdx.x;
    if (t < NEDGES_C) atomicAdd(&g_counts[adj_rows[t]], 1);

    // Copy emb rows into the left half of out. i indexes float4s of the
    // concatenated emb (user then item): row = i>>4, quarter = i&15.
    const float4* uef = (const float4*)user_emb;
    const float4* ief = (const float4*)item_emb;
    float4*       of  = (float4*)out;
    for (int i = t; i < NN_C * 16; i += EB * 256) {
        float4 v = (i < N_USERS_C * 16) ? __ldg(&uef[i])
                                        : __ldg(&ief[i - N_USERS_C * 16]);
        of[(size_t)(i >> 4) * 32 + (i & 15)] = v;
    }
}

// ---------------------------------------------------------------------------
// K1: block-level exclusive scan of counts (shuffle-based); zeroes counts
// ---------------------------------------------------------------------------
__global__ void __launch_bounds__(1024)
k_scan1() {
    __shared__ int s_wsum[32];
    const int idx  = blockIdx.x * 1024 + threadIdx.x;
    const int w    = threadIdx.x >> 5;
    const int lane = threadIdx.x & 31;

    int v = (idx < NN_C) ? g_counts[idx] : 0;
    if (idx < NN_C) g_counts[idx] = 0;      // reset for bucket-cursor use

    int x = v;                               // inclusive warp scan
    #pragma unroll
    for (int d = 1; d < 32; d <<= 1) {
        int y = __shfl_up_sync(0xffffffffu, x, d);
        if (lane >= d) x += y;
    }
    if (lane == 31) s_wsum[w] = x;
    __syncthreads();
    if (w == 0) {                            // scan the 32 warp sums
        int y = s_wsum[lane];
        int z = y;
        #pragma unroll
        for (int d = 1; d < 32; d <<= 1) {
            int u = __shfl_up_sync(0xffffffffu, z, d);
            if (lane >= d) z += u;
        }
        s_wsum[lane] = z - y;                // exclusive
        if (lane == 31) g_partials[blockIdx.x] = z;
    }
    __syncthreads();
    if (idx < NN_C) g_loc[idx] = x - v + s_wsum[w];
}

// K2: exclusive scan of the 293 block totals (one block, shuffle-based)
__global__ void __launch_bounds__(512)
k_scan2() {
    __shared__ int s_wsum[16];
    const int t = threadIdx.x;
    const int w = t >> 5, lane = t & 31;
    int v = (t < NB1) ? g_partials[t] : 0;
    int x = v;
    #pragma unroll
    for (int d = 1; d < 32; d <<= 1) {
        int y = __shfl_up_sync(0xffffffffu, x, d);
        if (lane >= d) x += y;
    }
    if (lane == 31) s_wsum[w] = x;
    __syncthreads();
    if (w == 0 && lane < 16) {
        int y = s_wsum[lane];
        int z = y;
        #pragma unroll
        for (int d = 1; d < 16; d <<= 1) {
            int u = __shfl_up_sync(0x0000ffffu, z, d);
            if (lane >= d) z += u;
        }
        s_wsum[lane] = z - y;
    }
    __syncthreads();
    if (t < NB1) g_partials[t] = x - v + s_wsum[w];
}

__device__ __forceinline__ int row_off(int r) {
    return (r < NN_C) ? (g_loc[r] + g_partials[r >> 10]) : NEDGES_C;
}

// ---------------------------------------------------------------------------
// K3: bucket edges into row-sorted CSR order
// ---------------------------------------------------------------------------
__global__ void __launch_bounds__(256)
k_bucket(const int* __restrict__ adj_rows,
         const int* __restrict__ adj_cols,
         const float* __restrict__ adj_vals) {
    int e = blockIdx.x * 256 + threadIdx.x;
    if (e >= NEDGES_C) return;
    int r = adj_rows[e];
    int pos = g_loc[r] + g_partials[r >> 10] + atomicAdd(&g_counts[r], 1);
    g_edges[pos] = make_int2(adj_cols[e], __float_as_int(adj_vals[e]));
}

// ---------------------------------------------------------------------------
// K4: fused segment-sum + finalize. One warp per row, lane owns 2 cols.
//     Edges prefetched warp-parallel (one coalesced load), broadcast via shfl;
//     per-edge float2 gathers then issue back-to-back.
//     Writes only out[:, 64:128] (emb half already written by K0).
// ---------------------------------------------------------------------------
__global__ void __launch_bounds__(256)
k_fused(const float* __restrict__ user_emb,
        const float* __restrict__ item_emb,
        const float* __restrict__ filt,
        float* __restrict__ out) {
    __shared__ float s_filt[D_C * D_C];   // general path only
    __shared__ float s_t[8][D_C];

    const int gen = g_general;            // uniform
    if (gen) {
        for (int i = threadIdx.x; i < D_C * D_C; i += blockDim.x)
            s_filt[i] = filt[i];
        __syncthreads();
    }

    const int w    = threadIdx.x >> 5;
    const int lane = threadIdx.x & 31;
    const int r    = blockIdx.x * 8 + w;  // 37500*8 == 300000

    const int start = row_off(r);
    const int end   = row_off(r + 1);
    if (lane == 0) g_counts[r] = 0;       // reset cursors for next replay

    float2 acc = make_float2(0.f, 0.f);
    for (int base = start; base < end; base += 32) {
        const int n = min(end - base, 32);
        int2 my = make_int2(0, 0);
        if (lane < n) my = g_edges[base + lane];   // one coalesced load
        for (int k = 0; k < n; k++) {
            int   col = __shfl_sync(0xffffffffu, my.x, k);
            float val = __int_as_float(__shfl_sync(0xffffffffu, my.y, k));
            const float2* src = (col < N_USERS_C)
                ? (const float2*)(user_emb + (size_t)col * D_C)
                : (const float2*)(item_emb + (size_t)(col - N_USERS_C) * D_C);
            float2 vv = __ldg(&src[lane]);         // 256B coalesced per warp
            acc.x = fmaf(val, vv.x, acc.x);
            acc.y = fmaf(val, vv.y, acc.y);
        }
    }

    const float2* esrc = (r < N_USERS_C)
        ? (const float2*)(user_emb + (size_t)r * D_C)
        : (const float2*)(item_emb + (size_t)(r - N_USERS_C) * D_C);
    float2 e = __ldg(&esrc[lane]);

    float2 t = make_float2(2.0f * e.x - acc.x, 2.0f * e.y - acc.y);

    float2 h;
    if (!gen) {
        h = t;
    } else {
        s_t[w][2 * lane]     = t.x;
        s_t[w][2 * lane + 1] = t.y;
        __syncwarp();
        float a0 = 0.f, a1 = 0.f;
        #pragma unroll 8
        for (int k = 0; k < D_C; k++) {
            float tk = s_t[w][k];
            a0 = fmaf(tk, s_filt[k * D_C + 2 * lane],     a0);
            a1 = fmaf(tk, s_filt[k * D_C + 2 * lane + 1], a1);
        }
        h = make_float2(a0, a1);
    }
    float2 sg = make_float2(1.0f / (1.0f + __expf(-h.x)),
                            1.0f / (1.0f + __expf(-h.y)));
    *((float2*)(out + (size_t)r * 128 + 64) + lane) = sg;
}

// ---------------------------------------------------------------------------
// Launch. Inputs (metadata order):
//   0: adj_rows (i32 1.2M)  1: adj_cols (i32 1.2M)  2: adj_vals (f32 1.2M)
//   3: user_emb (f32 200000*64)  4: item_emb (f32 100000*64)  5: filt (64*64)
// Output: 300000 rows of [emb | h] (f32, 128 wide), users then items.
// ---------------------------------------------------------------------------
extern "C" void kernel_launch(void* const* d_in, const int* in_sizes, int n_in,
                              void* d_out, int out_size) {
    const int*   adj_rows = (const int*)  d_in[0];
    const int*   adj_cols = (const int*)  d_in[1];
    const float* adj_vals = (const float*)d_in[2];
    const float* user_emb = (const float*)d_in[3];
    const float* item_emb = (const float*)d_in[4];
    const float* filt     = (const float*)d_in[5];
    float* out = (float*)d_out;

    k_hist_copy<<<EB, 256>>>(adj_rows, filt, user_emb, item_emb, out);
    k_scan1    <<<NB1, 1024>>>();
    k_scan2    <<<1, 512>>>();
    k_bucket   <<<EB, 256>>>(adj_rows, adj_cols, adj_vals);
    k_fused    <<<NN_C / 8, 256>>>(user_emb, item_emb, filt, out);
}